// round 11
// baseline (speedup 1.0000x reference)
#include <cuda_runtime.h>
#include <math.h>

#define MAXB 16
#define PRE  2000
#define PREP 2048
#define POST 1000
#define BUCK 2048
#define FBCAP 4096
#define NWORD 32           // ceil(PRE/64)
#define NBIN 4096
#define T1F 0.988037109375f   // 4051/4096 exactly  (candidate cutoff)
#define T2F 0.994873046875f   // 4075/4096 exactly  (bucket split)

// ---------------- scratch (device globals; no allocation) ----------------
// Zero-initialized at module load; kScanOut re-zeros counters each run.
__device__ unsigned            g_selcnt[MAXB * 2];
__device__ unsigned long long  g_sel[MAXB * 2 * BUCK];
__device__ float4              g_nmsBoxes4[MAXB * PREP];
__device__ float               g_topScore[MAXB * PREP];
// transposed mask: word-major, row-minor -> coalesced stores, streaming reads
__device__ unsigned long long  g_maskT[(size_t)MAXB * NWORD * PREP];

__device__ __forceinline__ unsigned mono(float f) {
    unsigned u = __float_as_uint(f);
    return (u & 0x80000000u) ? ~u : (u | 0x80000000u);
}
__device__ __forceinline__ float imono(unsigned m) {
    unsigned u = (m & 0x80000000u) ? (m ^ 0x80000000u) : ~m;
    return __uint_as_float(u);
}

// Exact decode path — must match XLA op-for-op (separate mul/add roundings).
__device__ __forceinline__ float4 decodeBoxExact(float4 av, float4 dv) {
    float aw = __fsub_rn(av.z, av.x), ah = __fsub_rn(av.w, av.y);
    float ax = __fadd_rn(av.x, __fmul_rn(0.5f, aw));
    float ay = __fadd_rn(av.y, __fmul_rn(0.5f, ah));
    float dw = fminf(dv.z, 4.0f), dh = fminf(dv.w, 4.0f);
    float px = __fadd_rn(__fmul_rn(dv.x, aw), ax);
    float py = __fadd_rn(__fmul_rn(dv.y, ah), ay);
    float pw = __fmul_rn(expf(dw), aw);
    float ph = __fmul_rn(expf(dh), ah);
    float hx = __fmul_rn(0.5f, pw), hy = __fmul_rn(0.5f, ph);
    float x1 = __fsub_rn(px, hx), y1 = __fsub_rn(py, hy);
    float x2 = __fadd_rn(px, hx), y2 = __fadd_rn(py, hy);
    return make_float4(fminf(fmaxf(x1, 0.0f), 1024.0f),
                       fminf(fmaxf(y1, 0.0f), 1024.0f),
                       fminf(fmaxf(x2, 0.0f), 1024.0f),
                       fminf(fmaxf(y2, 0.0f), 1024.0f));
}
__device__ __forceinline__ bool validExact(float4 bx) {
    return (__fsub_rn(bx.z, bx.x) >= 16.0f) && (__fsub_rn(bx.w, bx.y) >= 16.0f);
}

__device__ __forceinline__ bool specFail(int b) {
    unsigned c0 = g_selcnt[b * 2], c1 = g_selcnt[b * 2 + 1];
    return !(c0 <= BUCK && c1 <= BUCK && c0 + c1 >= PRE);
}

// ---------------- 1. lazy decode + bucketed speculative push ----------------
__device__ __forceinline__ void pushWarp(bool v, unsigned key, unsigned a,
                                         unsigned* cnt, unsigned long long* buf, int lane) {
    unsigned pb = __ballot_sync(0xFFFFFFFFu, v);
    if (!pb) return;
    int leader = __ffs(pb) - 1;
    unsigned base = 0;
    if (lane == leader) base = atomicAdd(cnt, (unsigned)__popc(pb));
    base = __shfl_sync(0xFFFFFFFFu, base, leader);
    if (v) {
        unsigned pos = base + (unsigned)__popc(pb & ((1u << lane) - 1u));
        if (pos < BUCK)
            buf[pos] = ((unsigned long long)key << 32) | (unsigned)(~a);
    }
}

__global__ void kDecode(const float* __restrict__ anc, const float* __restrict__ del,
                        const float* __restrict__ sco, int A, int nb) {
    int a0 = blockIdx.x * 256 + threadIdx.x;
    bool inb = (a0 < A);
    int a = inb ? a0 : (A - 1);
    int lane = threadIdx.x & 31;

    float4 av = ((const float4*)anc)[a];
    float aw = __fsub_rn(av.z, av.x), ah = __fsub_rn(av.w, av.y);
    float ax = __fadd_rn(av.x, __fmul_rn(0.5f, aw));
    float ay = __fadd_rn(av.y, __fmul_rn(0.5f, ah));

    for (int b = 0; b < nb; ++b) {
        float s = sco[(size_t)b * A + a];
        bool cand = inb && (s >= T1F);
        unsigned bal = __ballot_sync(0xFFFFFFFFu, cand);
        if (!bal) continue;

        float4 dv = ((const float4*)del)[(size_t)b * A + a];
        float dw = fminf(dv.z, 4.0f), dh = fminf(dv.w, 4.0f);
        float px = __fadd_rn(__fmul_rn(dv.x, aw), ax);
        float py = __fadd_rn(__fmul_rn(dv.y, ah), ay);
        float pw = __fmul_rn(__expf(dw), aw);
        float ph = __fmul_rn(__expf(dh), ah);
        float hx = __fmul_rn(0.5f, pw), hy = __fmul_rn(0.5f, ph);
        float cw = __fsub_rn(fminf(__fadd_rn(px, hx), 1024.0f),
                             fmaxf(__fsub_rn(px, hx), 0.0f));
        float ch = __fsub_rn(fminf(__fadd_rn(py, hy), 1024.0f),
                             fmaxf(__fsub_rn(py, hy), 0.0f));
        float mn = fminf(cw, ch);
        bool valid = false;
        if (cand) {
            if (mn >= 17.0f) valid = true;                 // sure-valid (1px margin)
            else if (mn >= 15.0f)                          // ambiguous -> exact
                valid = validExact(decodeBoxExact(av, dv));
        }
        unsigned key = __float_as_uint(s) | 0x80000000u;   // s > 0 -> mono
        bool hi = (s >= T2F);
        pushWarp(valid && hi,  key, (unsigned)a, &g_selcnt[b * 2],     &g_sel[(b * 2) * BUCK],     lane);
        pushWarp(valid && !hi, key, (unsigned)a, &g_selcnt[b * 2 + 1], &g_sel[(b * 2 + 1) * BUCK], lane);
    }
}

// ---------------- 2. sort (2048 bitonic, fused low stages) + re-decode winners ----
//     fb branch additionally runs the fused exact fallback (hist->select->collect)
#define CSW(x, y, d) { if (((x) < (y)) == (d)) { unsigned long long _t = (x); (x) = (y); (y) = _t; } }

__global__ void __launch_bounds__(512) kSort(const float* __restrict__ anc,
                                             const float* __restrict__ del,
                                             const float* __restrict__ sco, int A) {
    __shared__ unsigned long long s[FBCAP];     // spec path uses first 2048
    int bid = blockIdx.x;
    int b = bid >> 1, u = bid & 1;
    int t = threadIdx.x;                        // 512 threads
    bool fb = specFail(b);

    if (!fb) {
        unsigned cnt = min(g_selcnt[b * 2 + u], (unsigned)BUCK);
        const unsigned long long* src = &g_sel[(b * 2 + u) * BUCK];
        {
            int i0 = 4 * t;
            unsigned long long e0 = (i0 + 0 < (int)cnt) ? src[i0 + 0] : 0ull;
            unsigned long long e1 = (i0 + 1 < (int)cnt) ? src[i0 + 1] : 0ull;
            unsigned long long e2 = (i0 + 2 < (int)cnt) ? src[i0 + 2] : 0ull;
            unsigned long long e3 = (i0 + 3 < (int)cnt) ? src[i0 + 3] : 0ull;
            CSW(e0, e1, true); CSW(e2, e3, false);           // k=2
            bool d4 = ((i0 & 4) == 0);                        // k=4
            CSW(e0, e2, d4); CSW(e1, e3, d4);
            CSW(e0, e1, d4); CSW(e2, e3, d4);
            s[i0] = e0; s[i0 + 1] = e1; s[i0 + 2] = e2; s[i0 + 3] = e3;
        }
        __syncthreads();
        for (int k = 8; k <= BUCK; k <<= 1) {
            for (int j = k >> 1; j >= 4; j >>= 1) {
                for (int i = t; i < BUCK; i += 512) {
                    int l = i ^ j;
                    if (l > i) {
                        bool dir = ((i & k) == 0);
                        unsigned long long x = s[i], y = s[l];
                        if ((x < y) == dir) { s[i] = y; s[l] = x; }
                    }
                }
                __syncthreads();
            }
            {   // fused j=2, j=1 in registers
                int i0 = 4 * t;
                bool d = ((i0 & k) == 0);
                unsigned long long e0 = s[i0], e1 = s[i0 + 1], e2 = s[i0 + 2], e3 = s[i0 + 3];
                CSW(e0, e2, d); CSW(e1, e3, d);
                CSW(e0, e1, d); CSW(e2, e3, d);
                s[i0] = e0; s[i0 + 1] = e1; s[i0 + 2] = e2; s[i0 + 3] = e3;
            }
            __syncthreads();
        }
        unsigned off = u ? g_selcnt[b * 2] : 0u;      // c0 <= BUCK given !fb
        for (int i = t; i < (int)cnt; i += 512) {
            int pos = (int)off + i;
            if (pos >= PRE) continue;
            unsigned long long v = s[i];
            unsigned key = (unsigned)(v >> 32);
            unsigned a = ~(unsigned)(v & 0xFFFFFFFFull);
            float4 av = ((const float4*)anc)[a];
            float4 dv = ((const float4*)del)[(size_t)b * A + a];
            g_nmsBoxes4[b * PREP + pos] = decodeBoxExact(av, dv);
            g_topScore[b * PREP + pos] = imono(key);
        }
    } else {
        if (u == 1) return;
        // ---- fused exact fallback (hist -> threshold -> collect), then sort ----
        __shared__ unsigned shCnt, shT;
        unsigned* hist = (unsigned*)s;              // alias: hist phase precedes sort
        for (int i = t; i < NBIN; i += 512) hist[i] = 0;
        if (t == 0) shCnt = 0;
        __syncthreads();
        for (int a = t; a < A; a += 512) {
            float4 av = ((const float4*)anc)[a];
            float4 dv = ((const float4*)del)[(size_t)b * A + a];
            if (!validExact(decodeBoxExact(av, dv))) continue;
            float sc = sco[(size_t)b * A + a];
            int bin = (int)(__fmul_rn(sc, 4096.0f));
            bin = max(0, min(NBIN - 1, bin));
            atomicAdd(&hist[bin], 1u);
        }
        __syncthreads();
        if (t == 0) {
            unsigned cum = 0;
            int bin = NBIN - 1;
            for (; bin >= 0; --bin) { cum += hist[bin]; if (cum >= PRE) break; }
            shT = (unsigned)max(bin, 0);
        }
        __syncthreads();
        unsigned T = shT;
        for (int i = t; i < FBCAP; i += 512) s[i] = 0ull;
        __syncthreads();
        for (int a = t; a < A; a += 512) {
            float sc = sco[(size_t)b * A + a];
            int bin = (int)(__fmul_rn(sc, 4096.0f));
            bin = max(0, min(NBIN - 1, bin));
            if ((unsigned)bin < T) continue;
            float4 av = ((const float4*)anc)[a];
            float4 dv = ((const float4*)del)[(size_t)b * A + a];
            if (!validExact(decodeBoxExact(av, dv))) continue;
            unsigned p = atomicAdd(&shCnt, 1u);
            if (p < FBCAP)
                s[p] = ((unsigned long long)mono(sc) << 32) | (unsigned)(~(unsigned)a);
        }
        __syncthreads();
        for (int k = 2; k <= FBCAP; k <<= 1) {
            for (int j = k >> 1; j > 0; j >>= 1) {
                for (int i = t; i < FBCAP; i += 512) {
                    int l = i ^ j;
                    if (l > i) {
                        bool dir = ((i & k) == 0);
                        unsigned long long x = s[i], y = s[l];
                        if ((x < y) == dir) { s[i] = y; s[l] = x; }
                    }
                }
                __syncthreads();
            }
        }
        for (int i = t; i < PRE; i += 512) {
            unsigned long long v = s[i];
            if (v) {
                unsigned key = (unsigned)(v >> 32);
                unsigned a = ~(unsigned)(v & 0xFFFFFFFFull);
                float4 av = ((const float4*)anc)[a];
                float4 dv = ((const float4*)del)[(size_t)b * A + a];
                g_nmsBoxes4[b * PREP + i] = decodeBoxExact(av, dv);
                g_topScore[b * PREP + i] = imono(key);
            } else {
                g_nmsBoxes4[b * PREP + i] = make_float4(0.f, 0.f, 0.f, 0.f);
                g_topScore[b * PREP + i] = __int_as_float(0xFF800000);   // -inf
            }
        }
    }
}

// ---------------- 3. NMS bitmask: algebraic margin test, coalesced store --------
// r = inter - 0.7*den  ==  1.7*inter - (0.7*aI + 0.7*(aJ + 1e-6))
__device__ __forceinline__ void iouHalf(float4 mb, float ci, const float4* cb,
                                        const float* cf, int jlo, int jhi, int base,
                                        unsigned& m, unsigned& amb) {
    #pragma unroll 8
    for (int jj = jlo; jj < jhi; ++jj) {
        float4 ob = cb[base + jj];
        float cj = cf[base + jj];
        float ltx = fmaxf(mb.x, ob.x), lty = fmaxf(mb.y, ob.y);
        float rbx = fminf(mb.z, ob.z), rby = fminf(mb.w, ob.w);
        float w = fmaxf(__fsub_rn(rbx, ltx), 0.0f);
        float h = fmaxf(__fsub_rn(rby, lty), 0.0f);
        float inter = __fmul_rn(w, h);
        float cij = __fadd_rn(ci, cj);
        float r = __fmaf_rn(1.7f, inter, -cij);
        float eps = __fmul_rn(2e-6f, cij);
        unsigned bit = 1u << jj;
        if (r > eps) m |= bit;                       // sure-suppress
        else if (r >= -eps) amb |= bit;              // ambiguous (rare) -> exact fixup
    }
}

__global__ void kMask() {
    int b = blockIdx.z, ib = blockIdx.x, jb = blockIdx.y;
    if (jb < ib) return;
    __shared__ float4 cb[64];
    __shared__ float  cf[64];
    int t = threadIdx.x;
    int j0 = jb * 64;
    int jmax = min(64, PRE - j0);
    if (t < jmax) {
        float4 o = g_nmsBoxes4[b * PREP + j0 + t];
        cb[t] = o;
        float aj = __fmul_rn(__fsub_rn(o.z, o.x), __fsub_rn(o.w, o.y));
        cf[t] = __fmul_rn(0.7f, __fadd_rn(aj, 1e-6f));
    }
    __syncthreads();
    int i = ib * 64 + t;
    if (i >= PRE) return;
    float4 mb = g_nmsBoxes4[b * PREP + i];
    float areaI = __fmul_rn(__fsub_rn(mb.z, mb.x), __fsub_rn(mb.w, mb.y));
    float ci = __fmul_rn(0.7f, areaI);
    int jstart = (ib == jb) ? t + 1 : 0;
    unsigned m0 = 0, m1 = 0, a0 = 0, a1 = 0;
    if (jstart < 32) iouHalf(mb, ci, cb, cf, jstart, min(jmax, 32), 0, m0, a0);
    int lo1 = max(jstart - 32, 0);
    if (jmax > 32) iouHalf(mb, ci, cb, cf, lo1, jmax - 32, 32, m1, a1);
    unsigned long long amb = ((unsigned long long)a1 << 32) | a0;
    unsigned long long m = ((unsigned long long)m1 << 32) | m0;
    while (amb) {                                    // exact-div fixup (rare)
        int jj = __ffsll((long long)amb) - 1;
        amb &= amb - 1;
        float4 ob = cb[jj];
        float aJ = __fmul_rn(__fsub_rn(ob.z, ob.x), __fsub_rn(ob.w, ob.y));
        float ltx = fmaxf(mb.x, ob.x), lty = fmaxf(mb.y, ob.y);
        float rbx = fminf(mb.z, ob.z), rby = fminf(mb.w, ob.w);
        float w = fmaxf(__fsub_rn(rbx, ltx), 0.0f);
        float h = fmaxf(__fsub_rn(rby, lty), 0.0f);
        float inter = __fmul_rn(w, h);
        float den = __fadd_rn(__fsub_rn(__fadd_rn(areaI, aJ), inter), 1e-6f);
        if (__fdiv_rn(inter, den) > 0.7f) m |= (1ull << jj);
    }
    // transposed, coalesced: consecutive threads -> consecutive addresses
    g_maskT[((size_t)b * NWORD + jb) * PREP + i] = m;
}

// ---------------- 4. greedy scan (register ring, static indices) + output --------
__global__ void __launch_bounds__(32) kScanOut(float* __restrict__ out) {
    int b = blockIdx.x, t = threadIdx.x;        // 32 threads
    const unsigned long long* base = g_maskT + (size_t)b * NWORD * PREP;
    const unsigned long long* colC = base + (size_t)t * PREP;   // lane's word column
    unsigned long long rem = 0, useMask = 0;
    unsigned long long lw = 0;                  // window: local >> ((c&3)*16)
    unsigned long long localFull = 0;
    unsigned long long bufC[16], bufD[16];
    #pragma unroll
    for (int d = 0; d < 16; ++d) {
        bufC[d] = colC[d];
        bufD[d] = base[d];                      // word 0, rows 0..15
    }
    int kept = 0;
    for (int c = 0; c < PRE / 16; ++c) {        // 125 chunks of 16 rows
        int sh = (c & 3) * 16;
        if (sh == 0) {
            int w = c >> 2;
            localFull = __shfl_sync(0xFFFFFFFFu, rem, w);
            useMask = (t >= w) ? ~0ull : 0ull;  // lower words unwritten -> masked
        }
        lw = localFull >> sh;
        int i0 = c * 16;
        #pragma unroll
        for (int u = 0; u < 16; ++u) {
            int i = i0 + u;
            unsigned long long cur = bufC[u], dg = bufD[u];
            int nx = i + 16;                    // nx < 2016 <= PREP: safe read
            bufC[u] = colC[nx];
            bufD[u] = base[((size_t)(nx >> 6)) * PREP + nx];
            if (!((lw >> u) & 1ull)) {          // uniform across warp
                rem |= cur & useMask;
                lw |= (dg >> sh);
                localFull |= dg;
                ++kept;
            }
        }
        if (kept >= POST) break;                // later rows can't enter the output
    }
    // rank + write output (warp-level popcount prefix)
    unsigned long long vm = (t == NWORD - 1) ? 0xFFFFull : ~0ull;   // rows < PRE
    unsigned long long kw = (~rem) & vm;
    int cpop = __popcll(kw);
    int inc = cpop;
    #pragma unroll
    for (int d = 1; d < 32; d <<= 1) {
        int o = __shfl_up_sync(0xFFFFFFFFu, inc, d);
        if (t >= d) inc += o;
    }
    int excl = inc - cpop;
    int total = __shfl_sync(0xFFFFFFFFu, inc, 31);
    float* ob = out + (size_t)b * POST * 5;
    unsigned long long w2 = kw;
    while (w2) {
        int bit = __ffsll((long long)w2) - 1;
        w2 &= w2 - 1;
        int r = excl + __popcll(kw & ((1ull << bit) - 1ull));
        if (r >= POST) break;
        int i = t * 64 + bit;
        float s = g_topScore[b * PREP + i];
        float4 bx = g_nmsBoxes4[b * PREP + i];
        bool fin = isfinite(s);
        ob[r * 5 + 0] = fin ? bx.x : 0.f;
        ob[r * 5 + 1] = fin ? bx.y : 0.f;
        ob[r * 5 + 2] = fin ? bx.z : 0.f;
        ob[r * 5 + 3] = fin ? bx.w : 0.f;
        ob[r * 5 + 4] = fin ? s    : 0.f;
    }
    // zero-fill (only reachable when no early-break happened -> total exact)
    for (int r = total + t; r < POST; r += 32) {
        ob[r * 5 + 0] = 0.f; ob[r * 5 + 1] = 0.f;
        ob[r * 5 + 2] = 0.f; ob[r * 5 + 3] = 0.f;
        ob[r * 5 + 4] = 0.f;
    }
    // reset counters for the next replay (globals are zero-init on first run)
    if (t == 0) {
        g_selcnt[b * 2] = 0;
        g_selcnt[b * 2 + 1] = 0;
    }
}

// ---------------- launch ----------------
extern "C" void kernel_launch(void* const* d_in, const int* in_sizes, int n_in,
                              void* d_out, int out_size) {
    const float* anchors = (const float*)d_in[0];
    const float* deltas  = (const float*)d_in[1];
    const float* scores  = (const float*)d_in[2];
    float* out = (float*)d_out;
    int A = in_sizes[0] / 4;
    int B = in_sizes[2] / A;

    kDecode<<<(A + 255) / 256, 256>>>(anchors, deltas, scores, A, B);
    kSort<<<B * 2, 512>>>(anchors, deltas, scores, A);

    dim3 mg((PRE + 63) / 64, (PRE + 63) / 64, B);
    kMask<<<mg, 64>>>();
    kScanOut<<<B, 32>>>(out);
}

// round 13
// speedup vs baseline: 1.5776x; 1.5776x over previous
#include <cuda_runtime.h>
#include <math.h>

#define MAXB 16
#define PRE  2000
#define PREP 2048
#define POST 1000
#define BUCK 2048
#define FBCAP 4096
#define NWORD 32           // ceil(PRE/64)
#define NBIN 4096
#define T1F 0.988037109375f   // 4051/4096 exactly  (candidate cutoff)
#define T2F 0.994873046875f   // 4075/4096 exactly  (bucket split)

// ---------------- scratch (device globals; no allocation) ----------------
// Zero-initialized at module load; kScanOut re-zeros counters each run.
__device__ unsigned            g_selcnt[MAXB * 2];
__device__ unsigned long long  g_sel[MAXB * 2 * BUCK];
__device__ float4              g_nmsBoxes4[MAXB * PREP];
__device__ float               g_topScore[MAXB * PREP];
// transposed mask: word-major, row-minor -> coalesced stores, streaming reads
__device__ unsigned long long  g_maskT[(size_t)MAXB * NWORD * PREP];

__device__ __forceinline__ unsigned mono(float f) {
    unsigned u = __float_as_uint(f);
    return (u & 0x80000000u) ? ~u : (u | 0x80000000u);
}
__device__ __forceinline__ float imono(unsigned m) {
    unsigned u = (m & 0x80000000u) ? (m ^ 0x80000000u) : ~m;
    return __uint_as_float(u);
}

// Exact decode path — must match XLA op-for-op (separate mul/add roundings).
__device__ __forceinline__ float4 decodeBoxExact(float4 av, float4 dv) {
    float aw = __fsub_rn(av.z, av.x), ah = __fsub_rn(av.w, av.y);
    float ax = __fadd_rn(av.x, __fmul_rn(0.5f, aw));
    float ay = __fadd_rn(av.y, __fmul_rn(0.5f, ah));
    float dw = fminf(dv.z, 4.0f), dh = fminf(dv.w, 4.0f);
    float px = __fadd_rn(__fmul_rn(dv.x, aw), ax);
    float py = __fadd_rn(__fmul_rn(dv.y, ah), ay);
    float pw = __fmul_rn(expf(dw), aw);
    float ph = __fmul_rn(expf(dh), ah);
    float hx = __fmul_rn(0.5f, pw), hy = __fmul_rn(0.5f, ph);
    float x1 = __fsub_rn(px, hx), y1 = __fsub_rn(py, hy);
    float x2 = __fadd_rn(px, hx), y2 = __fadd_rn(py, hy);
    return make_float4(fminf(fmaxf(x1, 0.0f), 1024.0f),
                       fminf(fmaxf(y1, 0.0f), 1024.0f),
                       fminf(fmaxf(x2, 0.0f), 1024.0f),
                       fminf(fmaxf(y2, 0.0f), 1024.0f));
}
__device__ __forceinline__ bool validExact(float4 bx) {
    return (__fsub_rn(bx.z, bx.x) >= 16.0f) && (__fsub_rn(bx.w, bx.y) >= 16.0f);
}

__device__ __forceinline__ bool specFail(int b) {
    unsigned c0 = g_selcnt[b * 2], c1 = g_selcnt[b * 2 + 1];
    return !(c0 <= BUCK && c1 <= BUCK && c0 + c1 >= PRE);
}

// ---------------- 1. lazy decode + bucketed speculative push ----------------
__device__ __forceinline__ void pushWarp(bool v, unsigned key, unsigned a,
                                         unsigned* cnt, unsigned long long* buf, int lane) {
    unsigned pb = __ballot_sync(0xFFFFFFFFu, v);
    if (!pb) return;
    int leader = __ffs(pb) - 1;
    unsigned base = 0;
    if (lane == leader) base = atomicAdd(cnt, (unsigned)__popc(pb));
    base = __shfl_sync(0xFFFFFFFFu, base, leader);
    if (v) {
        unsigned pos = base + (unsigned)__popc(pb & ((1u << lane) - 1u));
        if (pos < BUCK)
            buf[pos] = ((unsigned long long)key << 32) | (unsigned)(~a);
    }
}

__global__ void kDecode(const float* __restrict__ anc, const float* __restrict__ del,
                        const float* __restrict__ sco, int A, int nb) {
    int a0 = blockIdx.x * 256 + threadIdx.x;
    bool inb = (a0 < A);
    int a = inb ? a0 : (A - 1);
    int lane = threadIdx.x & 31;

    float4 av = ((const float4*)anc)[a];
    float aw = __fsub_rn(av.z, av.x), ah = __fsub_rn(av.w, av.y);
    float ax = __fadd_rn(av.x, __fmul_rn(0.5f, aw));
    float ay = __fadd_rn(av.y, __fmul_rn(0.5f, ah));

    for (int b = 0; b < nb; ++b) {
        float s = sco[(size_t)b * A + a];
        bool cand = inb && (s >= T1F);
        unsigned bal = __ballot_sync(0xFFFFFFFFu, cand);
        if (!bal) continue;

        float4 dv = ((const float4*)del)[(size_t)b * A + a];
        float dw = fminf(dv.z, 4.0f), dh = fminf(dv.w, 4.0f);
        float px = __fadd_rn(__fmul_rn(dv.x, aw), ax);
        float py = __fadd_rn(__fmul_rn(dv.y, ah), ay);
        float pw = __fmul_rn(__expf(dw), aw);
        float ph = __fmul_rn(__expf(dh), ah);
        float hx = __fmul_rn(0.5f, pw), hy = __fmul_rn(0.5f, ph);
        float cw = __fsub_rn(fminf(__fadd_rn(px, hx), 1024.0f),
                             fmaxf(__fsub_rn(px, hx), 0.0f));
        float ch = __fsub_rn(fminf(__fadd_rn(py, hy), 1024.0f),
                             fmaxf(__fsub_rn(py, hy), 0.0f));
        float mn = fminf(cw, ch);
        bool valid = false;
        if (cand) {
            if (mn >= 17.0f) valid = true;                 // sure-valid (1px margin)
            else if (mn >= 15.0f)                          // ambiguous -> exact
                valid = validExact(decodeBoxExact(av, dv));
        }
        unsigned key = __float_as_uint(s) | 0x80000000u;   // s > 0 -> mono
        bool hi = (s >= T2F);
        pushWarp(valid && hi,  key, (unsigned)a, &g_selcnt[b * 2],     &g_sel[(b * 2) * BUCK],     lane);
        pushWarp(valid && !hi, key, (unsigned)a, &g_selcnt[b * 2 + 1], &g_sel[(b * 2 + 1) * BUCK], lane);
    }
}

// ---------------- 2. sort (2048 bitonic, fused low stages) + re-decode winners ----
//     fb branch additionally runs the fused exact fallback (hist->select->collect)
#define CSW(x, y, d) { if (((x) < (y)) == (d)) { unsigned long long _t = (x); (x) = (y); (y) = _t; } }

__global__ void __launch_bounds__(512) kSort(const float* __restrict__ anc,
                                             const float* __restrict__ del,
                                             const float* __restrict__ sco, int A) {
    __shared__ unsigned long long s[FBCAP];     // spec path uses first 2048
    int bid = blockIdx.x;
    int b = bid >> 1, u = bid & 1;
    int t = threadIdx.x;                        // 512 threads
    bool fb = specFail(b);

    if (!fb) {
        unsigned cnt = min(g_selcnt[b * 2 + u], (unsigned)BUCK);
        const unsigned long long* src = &g_sel[(b * 2 + u) * BUCK];
        {
            int i0 = 4 * t;
            unsigned long long e0 = (i0 + 0 < (int)cnt) ? src[i0 + 0] : 0ull;
            unsigned long long e1 = (i0 + 1 < (int)cnt) ? src[i0 + 1] : 0ull;
            unsigned long long e2 = (i0 + 2 < (int)cnt) ? src[i0 + 2] : 0ull;
            unsigned long long e3 = (i0 + 3 < (int)cnt) ? src[i0 + 3] : 0ull;
            CSW(e0, e1, true); CSW(e2, e3, false);           // k=2
            bool d4 = ((i0 & 4) == 0);                        // k=4
            CSW(e0, e2, d4); CSW(e1, e3, d4);
            CSW(e0, e1, d4); CSW(e2, e3, d4);
            s[i0] = e0; s[i0 + 1] = e1; s[i0 + 2] = e2; s[i0 + 3] = e3;
        }
        __syncthreads();
        for (int k = 8; k <= BUCK; k <<= 1) {
            for (int j = k >> 1; j >= 4; j >>= 1) {
                for (int i = t; i < BUCK; i += 512) {
                    int l = i ^ j;
                    if (l > i) {
                        bool dir = ((i & k) == 0);
                        unsigned long long x = s[i], y = s[l];
                        if ((x < y) == dir) { s[i] = y; s[l] = x; }
                    }
                }
                __syncthreads();
            }
            {   // fused j=2, j=1 in registers
                int i0 = 4 * t;
                bool d = ((i0 & k) == 0);
                unsigned long long e0 = s[i0], e1 = s[i0 + 1], e2 = s[i0 + 2], e3 = s[i0 + 3];
                CSW(e0, e2, d); CSW(e1, e3, d);
                CSW(e0, e1, d); CSW(e2, e3, d);
                s[i0] = e0; s[i0 + 1] = e1; s[i0 + 2] = e2; s[i0 + 3] = e3;
            }
            __syncthreads();
        }
        unsigned off = u ? g_selcnt[b * 2] : 0u;      // c0 <= BUCK given !fb
        for (int i = t; i < (int)cnt; i += 512) {
            int pos = (int)off + i;
            if (pos >= PRE) continue;
            unsigned long long v = s[i];
            unsigned key = (unsigned)(v >> 32);
            unsigned a = ~(unsigned)(v & 0xFFFFFFFFull);
            float4 av = ((const float4*)anc)[a];
            float4 dv = ((const float4*)del)[(size_t)b * A + a];
            g_nmsBoxes4[b * PREP + pos] = decodeBoxExact(av, dv);
            g_topScore[b * PREP + pos] = imono(key);
        }
    } else {
        if (u == 1) return;
        // ---- fused exact fallback (hist -> threshold -> collect), then sort ----
        __shared__ unsigned shCnt, shT;
        unsigned* hist = (unsigned*)s;              // alias: hist phase precedes sort
        for (int i = t; i < NBIN; i += 512) hist[i] = 0;
        if (t == 0) shCnt = 0;
        __syncthreads();
        for (int a = t; a < A; a += 512) {
            float4 av = ((const float4*)anc)[a];
            float4 dv = ((const float4*)del)[(size_t)b * A + a];
            if (!validExact(decodeBoxExact(av, dv))) continue;
            float sc = sco[(size_t)b * A + a];
            int bin = (int)(__fmul_rn(sc, 4096.0f));
            bin = max(0, min(NBIN - 1, bin));
            atomicAdd(&hist[bin], 1u);
        }
        __syncthreads();
        if (t == 0) {
            unsigned cum = 0;
            int bin = NBIN - 1;
            for (; bin >= 0; --bin) { cum += hist[bin]; if (cum >= PRE) break; }
            shT = (unsigned)max(bin, 0);
        }
        __syncthreads();
        unsigned T = shT;
        for (int i = t; i < FBCAP; i += 512) s[i] = 0ull;
        __syncthreads();
        for (int a = t; a < A; a += 512) {
            float sc = sco[(size_t)b * A + a];
            int bin = (int)(__fmul_rn(sc, 4096.0f));
            bin = max(0, min(NBIN - 1, bin));
            if ((unsigned)bin < T) continue;
            float4 av = ((const float4*)anc)[a];
            float4 dv = ((const float4*)del)[(size_t)b * A + a];
            if (!validExact(decodeBoxExact(av, dv))) continue;
            unsigned p = atomicAdd(&shCnt, 1u);
            if (p < FBCAP)
                s[p] = ((unsigned long long)mono(sc) << 32) | (unsigned)(~(unsigned)a);
        }
        __syncthreads();
        for (int k = 2; k <= FBCAP; k <<= 1) {
            for (int j = k >> 1; j > 0; j >>= 1) {
                for (int i = t; i < FBCAP; i += 512) {
                    int l = i ^ j;
                    if (l > i) {
                        bool dir = ((i & k) == 0);
                        unsigned long long x = s[i], y = s[l];
                        if ((x < y) == dir) { s[i] = y; s[l] = x; }
                    }
                }
                __syncthreads();
            }
        }
        for (int i = t; i < PRE; i += 512) {
            unsigned long long v = s[i];
            if (v) {
                unsigned key = (unsigned)(v >> 32);
                unsigned a = ~(unsigned)(v & 0xFFFFFFFFull);
                float4 av = ((const float4*)anc)[a];
                float4 dv = ((const float4*)del)[(size_t)b * A + a];
                g_nmsBoxes4[b * PREP + i] = decodeBoxExact(av, dv);
                g_topScore[b * PREP + i] = imono(key);
            } else {
                g_nmsBoxes4[b * PREP + i] = make_float4(0.f, 0.f, 0.f, 0.f);
                g_topScore[b * PREP + i] = __int_as_float(0xFF800000);   // -inf
            }
        }
    }
}

// ---------------- 3. NMS bitmask: algebraic margin test, coalesced store --------
// r = inter - 0.7*den  ==  1.7*inter - (0.7*aI + 0.7*(aJ + 1e-6))
__device__ __forceinline__ void iouHalf(float4 mb, float ci, const float4* cb,
                                        const float* cf, int jlo, int jhi, int base,
                                        unsigned& m, unsigned& amb) {
    #pragma unroll 8
    for (int jj = jlo; jj < jhi; ++jj) {
        float4 ob = cb[base + jj];
        float cj = cf[base + jj];
        float ltx = fmaxf(mb.x, ob.x), lty = fmaxf(mb.y, ob.y);
        float rbx = fminf(mb.z, ob.z), rby = fminf(mb.w, ob.w);
        float w = fmaxf(__fsub_rn(rbx, ltx), 0.0f);
        float h = fmaxf(__fsub_rn(rby, lty), 0.0f);
        float inter = __fmul_rn(w, h);
        float cij = __fadd_rn(ci, cj);
        float r = __fmaf_rn(1.7f, inter, -cij);
        float eps = __fmul_rn(2e-6f, cij);
        unsigned bit = 1u << jj;
        if (r > eps) m |= bit;                       // sure-suppress
        else if (r >= -eps) amb |= bit;              // ambiguous (rare) -> exact fixup
    }
}

__global__ void kMask() {
    int b = blockIdx.z, ib = blockIdx.x, jb = blockIdx.y;
    if (jb < ib) return;
    __shared__ float4 cb[64];
    __shared__ float  cf[64];
    int t = threadIdx.x;
    int j0 = jb * 64;
    int jmax = min(64, PRE - j0);
    if (t < jmax) {
        float4 o = g_nmsBoxes4[b * PREP + j0 + t];
        cb[t] = o;
        float aj = __fmul_rn(__fsub_rn(o.z, o.x), __fsub_rn(o.w, o.y));
        cf[t] = __fmul_rn(0.7f, __fadd_rn(aj, 1e-6f));
    }
    __syncthreads();
    int i = ib * 64 + t;
    if (i >= PRE) return;
    float4 mb = g_nmsBoxes4[b * PREP + i];
    float areaI = __fmul_rn(__fsub_rn(mb.z, mb.x), __fsub_rn(mb.w, mb.y));
    float ci = __fmul_rn(0.7f, areaI);
    int jstart = (ib == jb) ? t + 1 : 0;
    unsigned m0 = 0, m1 = 0, a0 = 0, a1 = 0;
    if (jstart < 32) iouHalf(mb, ci, cb, cf, jstart, min(jmax, 32), 0, m0, a0);
    int lo1 = max(jstart - 32, 0);
    if (jmax > 32) iouHalf(mb, ci, cb, cf, lo1, jmax - 32, 32, m1, a1);
    unsigned long long amb = ((unsigned long long)a1 << 32) | a0;
    unsigned long long m = ((unsigned long long)m1 << 32) | m0;
    while (amb) {                                    // exact-div fixup (rare)
        int jj = __ffsll((long long)amb) - 1;
        amb &= amb - 1;
        float4 ob = cb[jj];
        float aJ = __fmul_rn(__fsub_rn(ob.z, ob.x), __fsub_rn(ob.w, ob.y));
        float ltx = fmaxf(mb.x, ob.x), lty = fmaxf(mb.y, ob.y);
        float rbx = fminf(mb.z, ob.z), rby = fminf(mb.w, ob.w);
        float w = fmaxf(__fsub_rn(rbx, ltx), 0.0f);
        float h = fmaxf(__fsub_rn(rby, lty), 0.0f);
        float inter = __fmul_rn(w, h);
        float den = __fadd_rn(__fsub_rn(__fadd_rn(areaI, aJ), inter), 1e-6f);
        if (__fdiv_rn(inter, den) > 0.7f) m |= (1ull << jj);
    }
    // transposed, coalesced: consecutive threads -> consecutive addresses
    g_maskT[((size_t)b * NWORD + jb) * PREP + i] = m;
}

// ---------------- 4. greedy scan: single load stream, shfl diagonal ----------
// Invariant: lane w's `rem` accumulates ALL suppression bits of word w as soon
// as they occur (its own `cur` IS the diagonal word for rows in word w), so the
// 16-row live window can be re-derived from __shfl(rem, w) at each chunk start.
__global__ void __launch_bounds__(32) kScanOut(float* __restrict__ out) {
    int b = blockIdx.x, t = threadIdx.x;        // 32 threads
    const unsigned long long* base = g_maskT + (size_t)b * NWORD * PREP;
    const unsigned long long* colC = base + (size_t)t * PREP;   // lane's word column
    unsigned long long rem = 0;
    unsigned long long bufC[16];
    #pragma unroll
    for (int d = 0; d < 16; ++d) bufC[d] = colC[d];
    int kept = 0;
    for (int c = 0; c < PRE / 16; ++c) {        // 125 chunks of 16 rows
        int w = c >> 2;
        int sh = (c & 3) * 16;
        unsigned long long useMask = (t >= w) ? ~0ull : 0ull;   // lower words unwritten
        unsigned lw = (unsigned)((__shfl_sync(0xFFFFFFFFu, rem, w) >> sh) & 0xFFFFull);
        unsigned long long curv[16];
        unsigned dgs[16];
        #pragma unroll
        for (int u = 0; u < 16; ++u) {
            curv[u] = bufC[u];
            dgs[u] = (unsigned)((__shfl_sync(0xFFFFFFFFu, bufC[u], w) >> sh) & 0xFFFFull);
        }
        #pragma unroll
        for (int u = 0; u < 16; ++u) {
            bufC[u] = colC[c * 16 + u + 16];    // < 2016 <= PREP: safe
            if (!((lw >> u) & 1u)) {            // uniform across warp
                rem |= curv[u] & useMask;
                lw |= dgs[u];
                ++kept;
            }
        }
        if (kept >= POST) break;                // later rows can't enter the output
    }
    // rank + write output (warp-level popcount prefix)
    unsigned long long vm = (t == NWORD - 1) ? 0xFFFFull : ~0ull;   // rows < PRE
    unsigned long long kw = (~rem) & vm;
    int cpop = __popcll(kw);
    int inc = cpop;
    #pragma unroll
    for (int d = 1; d < 32; d <<= 1) {
        int o = __shfl_up_sync(0xFFFFFFFFu, inc, d);
        if (t >= d) inc += o;
    }
    int excl = inc - cpop;
    int total = __shfl_sync(0xFFFFFFFFu, inc, 31);
    float* ob = out + (size_t)b * POST * 5;
    unsigned long long w2 = kw;
    while (w2) {
        int bit = __ffsll((long long)w2) - 1;
        w2 &= w2 - 1;
        int r = excl + __popcll(kw & ((1ull << bit) - 1ull));
        if (r >= POST) break;
        int i = t * 64 + bit;
        float s = g_topScore[b * PREP + i];
        float4 bx = g_nmsBoxes4[b * PREP + i];
        bool fin = isfinite(s);
        ob[r * 5 + 0] = fin ? bx.x : 0.f;
        ob[r * 5 + 1] = fin ? bx.y : 0.f;
        ob[r * 5 + 2] = fin ? bx.z : 0.f;
        ob[r * 5 + 3] = fin ? bx.w : 0.f;
        ob[r * 5 + 4] = fin ? s    : 0.f;
    }
    // zero-fill (only reachable when no early-break happened -> total exact)
    for (int r = total + t; r < POST; r += 32) {
        ob[r * 5 + 0] = 0.f; ob[r * 5 + 1] = 0.f;
        ob[r * 5 + 2] = 0.f; ob[r * 5 + 3] = 0.f;
        ob[r * 5 + 4] = 0.f;
    }
    // reset counters for the next replay (globals are zero-init on first run)
    if (t == 0) {
        g_selcnt[b * 2] = 0;
        g_selcnt[b * 2 + 1] = 0;
    }
}

// ---------------- launch ----------------
extern "C" void kernel_launch(void* const* d_in, const int* in_sizes, int n_in,
                              void* d_out, int out_size) {
    const float* anchors = (const float*)d_in[0];
    const float* deltas  = (const float*)d_in[1];
    const float* scores  = (const float*)d_in[2];
    float* out = (float*)d_out;
    int A = in_sizes[0] / 4;
    int B = in_sizes[2] / A;

    kDecode<<<(A + 255) / 256, 256>>>(anchors, deltas, scores, A, B);
    kSort<<<B * 2, 512>>>(anchors, deltas, scores, A);

    dim3 mg((PRE + 63) / 64, (PRE + 63) / 64, B);
    kMask<<<mg, 64>>>();
    kScanOut<<<B, 32>>>(out);
}